// round 10
// baseline (speedup 1.0000x reference)
#include <cuda_runtime.h>
#include <cuda_bf16.h>

// Lightcone-truncated quantum circuit simulation.
//
// Reference: 25-qubit state vector, 8 layers of (RY on every qubit, then
// CNOT chain w=0..23), output = sum_{MSB=0}|amp|^2 - sum_{MSB=1}|amp|^2
// = <Z_{qubit 0}> (qubit w maps to bit 24-w of the flat index; qubit 0 = MSB).
//
// Heisenberg-picture lightcone: conjugating Z_0 backward, support grows by at
// most one qubit per layer (X on a CNOT control spreads one step up; the
// C23..C0 conjugation order prevents cascading within a layer). After 8
// layers support is within qubits {0..7}. All gates outside the support
// conjugate trivially, so <Z_0> of the full circuit equals <Z_0> of the
// circuit truncated to the first NQS qubits (RYs on q0..NQS-1, CNOTs
// w=0..NQS-2). We use NQS=12 for a 4-qubit safety margin; the 4096-amplitude
// simulation runs entirely in one block's shared memory.

#define NQ     25
#define DEPTH  8
#define NQS    12
#define SIZE   (1 << NQS)
#define THREADS 256

__global__ void __launch_bounds__(THREADS, 1)
lightcone_qsim_kernel(const float* __restrict__ theta, float* __restrict__ out)
{
    __shared__ double st[SIZE];
    __shared__ double red[THREADS / 32];

    const int tid = threadIdx.x;

    // |0...0>
    for (int i = tid; i < SIZE; i += THREADS) st[i] = 0.0;
    __syncthreads();
    if (tid == 0) st[0] = 1.0;
    __syncthreads();

    for (int layer = 0; layer < DEPTH; ++layer) {
        // --- RY on qubits 0..NQS-1 (qubit w <-> bit NQS-1-w) ---
        for (int w = 0; w < NQS; ++w) {
            const int b    = NQS - 1 - w;
            const int mask = 1 << b;
            const double ang = 0.5 * (double)theta[layer * NQ + w];
            const double c = cos(ang);
            const double s = sin(ang);
            const int half = SIZE >> 1;
            for (int idx = tid; idx < half; idx += THREADS) {
                const int low = idx & (mask - 1);
                const int hi  = (idx >> b) << (b + 1);
                const int i0  = hi | low;
                const int i1  = i0 | mask;
                const double a0 = st[i0];
                const double a1 = st[i1];
                st[i0] = c * a0 - s * a1;
                st[i1] = s * a0 + c * a1;
            }
            __syncthreads();
        }
        // --- CNOT chain w=0..NQS-2 (control bit bc = NQS-1-w, target bt = bc-1) ---
        for (int w = 0; w < NQS - 1; ++w) {
            const int bt    = NQS - 2 - w;         // target bit
            const int cmask = 1 << (bt + 1);       // control bit mask
            const int tmask = 1 << bt;             // target bit mask
            const int quarter = SIZE >> 2;
            for (int idx = tid; idx < quarter; idx += THREADS) {
                const int low = idx & (tmask - 1);
                const int hi  = (idx >> bt) << (bt + 2);
                const int i0  = hi | cmask | low;  // control=1, target=0
                const int i1  = i0 | tmask;        // control=1, target=1
                const double a = st[i0];
                st[i0] = st[i1];
                st[i1] = a;
            }
            __syncthreads();
        }
    }

    // --- <Z_0> = sum_i (-1)^{MSB(i)} amp_i^2 ---
    double part = 0.0;
    for (int i = tid; i < SIZE; i += THREADS) {
        const double a = st[i];
        part += (i & (SIZE >> 1)) ? (-a * a) : (a * a);
    }
    #pragma unroll
    for (int off = 16; off > 0; off >>= 1)
        part += __shfl_down_sync(0xffffffffu, part, off);
    if ((tid & 31) == 0) red[tid >> 5] = part;
    __syncthreads();
    if (tid == 0) {
        double tot = 0.0;
        #pragma unroll
        for (int i = 0; i < THREADS / 32; ++i) tot += red[i];
        out[0] = (float)tot;
    }
}

extern "C" void kernel_launch(void* const* d_in, const int* in_sizes, int n_in,
                              void* d_out, int out_size)
{
    const float* theta = (const float*)d_in[0];   // [DEPTH, NQ] float32
    float* out = (float*)d_out;                   // scalar float32
    (void)in_sizes; (void)n_in; (void)out_size;
    lightcone_qsim_kernel<<<1, THREADS>>>(theta, out);
}

// round 11
// speedup vs baseline: 1.0036x; 1.0036x over previous
#include <cuda_runtime.h>
#include <cuda_bf16.h>

// Lightcone-truncated quantum circuit simulation.
//
// Reference: 25-qubit state vector, 8 layers of (RY on every qubit, then
// CNOT chain w=0..23), output = sum_{MSB=0}|amp|^2 - sum_{MSB=1}|amp|^2
// = <Z_{qubit 0}> (qubit w maps to bit 24-w of the flat index; qubit 0 = MSB).
//
// Heisenberg-picture lightcone: conjugating Z_0 backward, support grows by at
// most one qubit per layer (X on a CNOT control spreads one step up; the
// C23..C0 conjugation order prevents cascading within a layer). After 8
// layers support is within qubits {0..7}. All gates outside the support
// conjugate trivially, so <Z_0> of the full circuit equals <Z_0> of the
// circuit truncated to the first NQS qubits (RYs on q0..NQS-1, CNOTs
// w=0..NQS-2). We use NQS=12 for a 4-qubit safety margin; the 4096-amplitude
// simulation runs entirely in one block's shared memory.

#define NQ     25
#define DEPTH  8
#define NQS    12
#define SIZE   (1 << NQS)
#define THREADS 256

__global__ void __launch_bounds__(THREADS, 1)
lightcone_qsim_kernel(const float* __restrict__ theta, float* __restrict__ out)
{
    __shared__ double st[SIZE];
    __shared__ double red[THREADS / 32];

    const int tid = threadIdx.x;

    // |0...0>
    for (int i = tid; i < SIZE; i += THREADS) st[i] = 0.0;
    __syncthreads();
    if (tid == 0) st[0] = 1.0;
    __syncthreads();

    for (int layer = 0; layer < DEPTH; ++layer) {
        // --- RY on qubits 0..NQS-1 (qubit w <-> bit NQS-1-w) ---
        for (int w = 0; w < NQS; ++w) {
            const int b    = NQS - 1 - w;
            const int mask = 1 << b;
            const double ang = 0.5 * (double)theta[layer * NQ + w];
            const double c = cos(ang);
            const double s = sin(ang);
            const int half = SIZE >> 1;
            for (int idx = tid; idx < half; idx += THREADS) {
                const int low = idx & (mask - 1);
                const int hi  = (idx >> b) << (b + 1);
                const int i0  = hi | low;
                const int i1  = i0 | mask;
                const double a0 = st[i0];
                const double a1 = st[i1];
                st[i0] = c * a0 - s * a1;
                st[i1] = s * a0 + c * a1;
            }
            __syncthreads();
        }
        // --- CNOT chain w=0..NQS-2 (control bit bc = NQS-1-w, target bt = bc-1) ---
        for (int w = 0; w < NQS - 1; ++w) {
            const int bt    = NQS - 2 - w;         // target bit
            const int cmask = 1 << (bt + 1);       // control bit mask
            const int tmask = 1 << bt;             // target bit mask
            const int quarter = SIZE >> 2;
            for (int idx = tid; idx < quarter; idx += THREADS) {
                const int low = idx & (tmask - 1);
                const int hi  = (idx >> bt) << (bt + 2);
                const int i0  = hi | cmask | low;  // control=1, target=0
                const int i1  = i0 | tmask;        // control=1, target=1
                const double a = st[i0];
                st[i0] = st[i1];
                st[i1] = a;
            }
            __syncthreads();
        }
    }

    // --- <Z_0> = sum_i (-1)^{MSB(i)} amp_i^2 ---
    double part = 0.0;
    for (int i = tid; i < SIZE; i += THREADS) {
        const double a = st[i];
        part += (i & (SIZE >> 1)) ? (-a * a) : (a * a);
    }
    #pragma unroll
    for (int off = 16; off > 0; off >>= 1)
        part += __shfl_down_sync(0xffffffffu, part, off);
    if ((tid & 31) == 0) red[tid >> 5] = part;
    __syncthreads();
    if (tid == 0) {
        double tot = 0.0;
        #pragma unroll
        for (int i = 0; i < THREADS / 32; ++i) tot += red[i];
        out[0] = (float)tot;
    }
}

extern "C" void kernel_launch(void* const* d_in, const int* in_sizes, int n_in,
                              void* d_out, int out_size)
{
    const float* theta = (const float*)d_in[0];   // [DEPTH, NQ] float32
    float* out = (float*)d_out;                   // scalar float32
    (void)in_sizes; (void)n_in; (void)out_size;
    lightcone_qsim_kernel<<<1, THREADS>>>(theta, out);
}